// round 14
// baseline (speedup 1.0000x reference)
#include <cuda_runtime.h>
#include <cstdint>

constexpr int N_IN  = 256;
constexpr int BATCH = 4096;
constexpr int ITER  = 8;     // batches per thread
constexpr int GRP   = 8;     // single burst of 8 loads
constexpr int TPB   = 128;   // 64 matrices * 2 row-pairs per block
constexpr int QUART = 64;    // matrices per block

struct V8 { uint32_t r[8]; };

// non-volatile: let ptxas schedule
__device__ __forceinline__ V8 ldg256_el(const void* p) {
    V8 v;
    asm("ld.global.nc.L2::evict_last.v8.b32 {%0,%1,%2,%3,%4,%5,%6,%7}, [%8];"
        : "=r"(v.r[0]), "=r"(v.r[1]), "=r"(v.r[2]), "=r"(v.r[3]),
          "=r"(v.r[4]), "=r"(v.r[5]), "=r"(v.r[6]), "=r"(v.r[7])
        : "l"(p));
    return v;
}
__device__ __forceinline__ void stg256_ef(void* p, const V8& v) {
    asm volatile("st.global.L2::evict_first.v8.b32 [%0], {%1,%2,%3,%4,%5,%6,%7,%8};"
                 :: "l"(p),
                    "r"(v.r[0]), "r"(v.r[1]), "r"(v.r[2]), "r"(v.r[3]),
                    "r"(v.r[4]), "r"(v.r[5]), "r"(v.r[6]), "r"(v.r[7])
                 : "memory");
}

__global__ void __launch_bounds__(TPB) fused_kernel(
    const float* __restrict__ I,
    const float* __restrict__ aW,
    const float* __restrict__ uW,
    const float* __restrict__ tW,
    float* __restrict__ O)
{
    const int tid = threadIdx.x;
    const int q   = blockIdx.x & 3;           // which quarter of N_IN
    const int g   = blockIdx.x >> 2;          // batch group (0..511)

    // ---- build WM[n] in registers (MUFU fast path) ----
    const int n = q * QUART + (tid >> 1);

    float a  = aW[n];
    float ex = __expf(-uW[n * 3 + 0]);
    float ey = __expf(-uW[n * 3 + 1]);
    float ez = __expf(-uW[n * 3 + 2]);
    float ux = __frcp_rn(1.0f + ex);
    float uy = __frcp_rn(1.0f + ey);
    float uz = __frcp_rn(1.0f + ez);
    float inv = rsqrtf(fmaf(ux, ux, fmaf(uy, uy, uz * uz)));
    ux *= inv; uy *= inv; uz *= inv;

    float s = __sinf(a);
    float c = __cosf(a);

    // rows of WM; row3 = (0,0,0,1) folded into the FMA tree
    float4 r0, r1, r2;
    r0.x = (1.0f - ux * ux) * c + ux * ux;
    r0.y = -uz * s - ux * uy * c + ux * uy;
    r0.z =  uy * s - ux * uz * c + ux * uz;
    r0.w = tW[n * 3 + 0];
    r1.x =  uz * s - ux * uy * c + ux * uy;
    r1.y = (1.0f - uy * uy) * c + uy * uy;
    r1.z = -ux * s - uy * uz * c + uy * uz;
    r1.w = tW[n * 3 + 1];
    r2.x = -uy * s - ux * uz * c + ux * uz;
    r2.y =  ux * s - uy * uz * c + uy * uz;
    r2.z = (1.0f - uz * uz) * c + uz * uz;
    r2.w = tW[n * 3 + 2];

    // ---- single burst: 8 loads, then 8 compute+stores ----
    constexpr int STRIDE_F = N_IN * 16;        // 4096 floats per batch
    int fidx = g * (ITER * STRIDE_F) + n * 16 + (tid & 1) * 8;

    V8 in[GRP];
#pragma unroll
    for (int k = 0; k < GRP; k++) in[k] = ldg256_el(I + fidx + k * STRIDE_F);

#pragma unroll
    for (int k = 0; k < GRP; k++) {
        V8 ov;
#pragma unroll
        for (int half = 0; half < 2; half++) {
            float vx = __uint_as_float(in[k].r[half * 4 + 0]);
            float vy = __uint_as_float(in[k].r[half * 4 + 1]);
            float vz = __uint_as_float(in[k].r[half * 4 + 2]);
            float vw = __uint_as_float(in[k].r[half * 4 + 3]);
            ov.r[half * 4 + 0] = __float_as_uint(fmaf(vx, r0.x, fmaf(vy, r1.x, vz * r2.x)));
            ov.r[half * 4 + 1] = __float_as_uint(fmaf(vx, r0.y, fmaf(vy, r1.y, vz * r2.y)));
            ov.r[half * 4 + 2] = __float_as_uint(fmaf(vx, r0.z, fmaf(vy, r1.z, vz * r2.z)));
            ov.r[half * 4 + 3] = __float_as_uint(fmaf(vx, r0.w, fmaf(vy, r1.w, fmaf(vz, r2.w, vw))));
        }
        stg256_ef(O + fidx + k * STRIDE_F, ov);
    }
}

extern "C" void kernel_launch(void* const* d_in, const int* in_sizes, int n_in,
                              void* d_out, int out_size) {
    const float* I  = (const float*)d_in[0];
    const float* aW = (const float*)d_in[1];
    const float* uW = (const float*)d_in[2];
    const float* tW = (const float*)d_in[3];

    int blocks = (BATCH / ITER) * 4;   // 2048
    fused_kernel<<<blocks, TPB>>>(I, aW, uW, tW, (float*)d_out);
}